// round 10
// baseline (speedup 1.0000x reference)
#include <cuda_runtime.h>
#include <math.h>
#include <stdint.h>

#define D_MODEL 256
#define STATE_N 64
#define SEQ_L   8192
#define HALF_L  4096

// Scratch: K_hat[d, L] complex64 (16 MB) as a device global (no runtime alloc).
__device__ float2 g_Khat[D_MODEL * SEQ_L];

// ---------------------------------------------------------------------------
// tf32 helpers
// ---------------------------------------------------------------------------
__device__ __forceinline__ uint32_t tf32_rna(float x) {
    uint32_t u;
    asm("cvt.rna.tf32.f32 %0, %1;" : "=r"(u) : "f"(x));
    return u;
}

__device__ __forceinline__ void mma_tf32(float& d0, float& d1, float& d2, float& d3,
                                         uint32_t a0, uint32_t a1, uint32_t a2, uint32_t a3,
                                         uint32_t b0, uint32_t b1)
{
    asm volatile(
        "mma.sync.aligned.m16n8k8.row.col.f32.tf32.tf32.f32 "
        "{%0,%1,%2,%3}, {%4,%5,%6,%7}, {%8,%9}, {%0,%1,%2,%3};"
        : "+f"(d0), "+f"(d1), "+f"(d2), "+f"(d3)
        : "r"(a0), "r"(a1), "r"(a2), "r"(a3), "r"(b0), "r"(b1));
}

// ---------------------------------------------------------------------------
// Woodbury tail from the 8 fast-path sums (g purely imaginary form).
// ---------------------------------------------------------------------------
__device__ __forceinline__ float2 wb_fast(float SA, float SB, float SC, float SD,
                                          float TA, float TB, float TC, float TD,
                                          float pfr, float pfi)
{
    float PRBr = SA + TB, PRBi = SB - TA;
    float BRPr = SA - TB, BRPi = -SB - TA;
    float qr = 1.0f + SC, qi = -TC;
    float BRBr = SD, BRBi = -TD;
    float iq = 1.0f / (qr * qr + qi * qi);
    float numr = BRPr * PRBr - BRPi * PRBi;
    float numi = BRPr * PRBi + BRPi * PRBr;
    float tr = (numr * qr + numi * qi) * iq;
    float ti = (numi * qr - numr * qi) * iq;
    float hr = BRBr - tr, hi = BRBi - ti;
    return make_float2(pfr * hr - pfi * hi, pfr * hi + pfi * hr);
}

// ---------------------------------------------------------------------------
// Kernel 1: Cauchy + Woodbury via tf32 mma.sync.
//   D[16k, 8sums] += A_inv[16k, 8n] x Sw[8n, 8j]  +  A_Ri[16k, 8n] x Tw[8n, 8j]
// Sums cols: 0-3 = SA..SD (inv * {w1r*sp, w1i*sp, pp*sp, bb*sp}),
//            4-7 = TA..TD (Ri  * {w1r,    w1i,    pp,    bb}).
// blockIdx = (k-seg of 1024, d); 256 threads = 8 warps x 8 m16-tiles each.
// ---------------------------------------------------------------------------
__global__ void __launch_bounds__(256) cauchy_mma(
    const float* __restrict__ Lam_re, const float* __restrict__ Lam_im,
    const float* __restrict__ P_re,   const float* __restrict__ P_im,
    const float* __restrict__ B_re,   const float* __restrict__ B_im,
    const float* __restrict__ log_dt)
{
    __shared__ float2 s_lisp[STATE_N];     // (lam_im, sp*sp)
    __shared__ float  s_Sw[4 * STATE_N];   // tf32-rounded S-weights [j][n]
    __shared__ float  s_Tw[4 * STATE_N];   // tf32-rounded T-weights [j][n]
    __shared__ float  s_gi[1024], s_pfr[1024], s_pfi[1024];
    __shared__ float  s_sums[8][16][8];    // per-warp D staging
    __shared__ float  s_scal_sh;

    const int d    = blockIdx.y;
    const int seg  = blockIdx.x;
    const int tid  = threadIdx.x;
    const int lane = tid & 31;
    const int warp = tid >> 5;

    if (tid < STATE_N) {
        const int idx = d * STATE_N + tid;
        float lr = Lam_re[idx];
        float li = Lam_im[idx];
        float sp = fmaxf(lr, 0.0f) + log1pf(expf(-fabsf(lr)));  // softplus
        float pr = P_re[idx], pi = P_im[idx];
        float br = B_re[idx], bi = B_im[idx];
        float w1r = pr * br + pi * bi;    // conj(P)*B
        float w1i = pr * bi - pi * br;
        float pp  = pr * pr + pi * pi;
        float bb  = br * br + bi * bi;
        s_lisp[tid] = make_float2(li, sp * sp);
        s_Sw[0 * STATE_N + tid] = __uint_as_float(tf32_rna(w1r * sp));
        s_Sw[1 * STATE_N + tid] = __uint_as_float(tf32_rna(w1i * sp));
        s_Sw[2 * STATE_N + tid] = __uint_as_float(tf32_rna(pp * sp));
        s_Sw[3 * STATE_N + tid] = __uint_as_float(tf32_rna(bb * sp));
        s_Tw[0 * STATE_N + tid] = __uint_as_float(tf32_rna(w1r));
        s_Tw[1 * STATE_N + tid] = __uint_as_float(tf32_rna(w1i));
        s_Tw[2 * STATE_N + tid] = __uint_as_float(tf32_rna(pp));
        s_Tw[3 * STATE_N + tid] = __uint_as_float(tf32_rna(bb));
    }
    if (tid == 0) s_scal_sh = 2.0f * expf(-log_dt[d]);
    __syncthreads();

    // per-k prologue: gi, pref (f32 arithmetic matching the reference)
    const float scal = s_scal_sh;
    const float w0 = (float)(-6.283185307179586476925286766559 / (double)SEQ_L);
    for (int kk = tid; kk < 1024; kk += 256) {
        int k = seg * 1024 + kk;
        float zs, zc;
        sincosf(w0 * (float)k, &zs, &zc);
        float dzr = 1.0f + zc, dzi = zs;
        if (k == HALF_L) { dzr = 1.1920929e-7f; dzi = 0.0f; }
        float idm = 1.0f / (dzr * dzr + dzi * dzi);
        float nr = 1.0f - zc, ni = -zs;
        s_gi[kk]  = scal * (ni * dzr - nr * dzi) * idm;
        s_pfr[kk] = 2.0f * dzr * idm;
        s_pfi[kk] = -2.0f * dzi * idm;
    }
    __syncthreads();

    const int j  = lane >> 2;       // output sum column 0..7
    const int qr = lane & 3;

    for (int t = 0; t < 8; t++) {
        const int base = (warp * 8 + t) * 16;
        const float gi0 = s_gi[base + (lane >> 2)];       // row l/4
        const float gi1 = s_gi[base + 8 + (lane >> 2)];   // row 8 + l/4

        float d0 = 0.f, d1 = 0.f, d2 = 0.f, d3 = 0.f;

#pragma unroll
        for (int ch = 0; ch < 8; ch++) {
            const int n0 = ch * 8 + qr;
            const int n1 = n0 + 4;
            float2 cA = s_lisp[n0];
            float2 cB = s_lisp[n1];

            // 4 A-fragment sites: (row, n): a0=(r0,n0) a1=(r1,n0) a2=(r0,n1) a3=(r1,n1)
            float di0 = gi0 - cA.x;
            float di1 = gi1 - cA.x;
            float di2 = gi0 - cB.x;
            float di3 = gi1 - cB.x;
            float m0 = fmaf(di0, di0, cA.y);
            float m1 = fmaf(di1, di1, cA.y);
            float m2 = fmaf(di2, di2, cB.y);
            float m3 = fmaf(di3, di3, cB.y);
            float i0, i1, i2, i3;
            asm("rcp.approx.f32 %0, %1;" : "=f"(i0) : "f"(m0));
            asm("rcp.approx.f32 %0, %1;" : "=f"(i1) : "f"(m1));
            asm("rcp.approx.f32 %0, %1;" : "=f"(i2) : "f"(m2));
            asm("rcp.approx.f32 %0, %1;" : "=f"(i3) : "f"(m3));
            float r0 = di0 * i0, r1 = di1 * i1, r2 = di2 * i2, r3 = di3 * i3;

            uint32_t Ai0 = tf32_rna(i0), Ai1 = tf32_rna(i1);
            uint32_t Ai2 = tf32_rna(i2), Ai3 = tf32_rna(i3);
            uint32_t Ar0 = tf32_rna(r0), Ar1 = tf32_rna(r1);
            uint32_t Ar2 = tf32_rna(r2), Ar3 = tf32_rna(r3);

            // B fragments: b0 -> (n=n0, col=j), b1 -> (n=n1, col=j)
            float bs0, bs1, bt0, bt1;
            if (j < 4) {
                bs0 = s_Sw[j * STATE_N + n0];
                bs1 = s_Sw[j * STATE_N + n1];
                bt0 = 0.f; bt1 = 0.f;
            } else {
                bs0 = 0.f; bs1 = 0.f;
                bt0 = s_Tw[(j - 4) * STATE_N + n0];
                bt1 = s_Tw[(j - 4) * STATE_N + n1];
            }

            mma_tf32(d0, d1, d2, d3, Ai0, Ai1, Ai2, Ai3,
                     __float_as_uint(bs0), __float_as_uint(bs1));
            mma_tf32(d0, d1, d2, d3, Ar0, Ar1, Ar2, Ar3,
                     __float_as_uint(bt0), __float_as_uint(bt1));
        }

        // epilogue: stage D to smem, lanes 0..15 run Woodbury for 16 k's
        float (*sw)[8] = s_sums[warp];
        sw[lane >> 2][2 * qr]         = d0;
        sw[lane >> 2][2 * qr + 1]     = d1;
        sw[8 + (lane >> 2)][2 * qr]     = d2;
        sw[8 + (lane >> 2)][2 * qr + 1] = d3;
        __syncwarp();
        if (lane < 16) {
            float SA = sw[lane][0], SB = sw[lane][1];
            float SC = sw[lane][2], SD = sw[lane][3];
            float TA = sw[lane][4], TB = sw[lane][5];
            float TC = sw[lane][6], TD = sw[lane][7];
            int kk = base + lane;
            float2 r = wb_fast(SA, SB, SC, SD, TA, TB, TC, TD,
                               s_pfr[kk], s_pfi[kk]);
            g_Khat[d * SEQ_L + seg * 1024 + kk] = r;
        }
        __syncwarp();
    }
}

// ---------------------------------------------------------------------------
// Kernel 1b: exact recompute of the eps-clamped point k = L/2 (g real part
// huge there; fast path is invalid). One block per d, serial on lane 0.
// ---------------------------------------------------------------------------
__global__ void fix4096(
    const float* __restrict__ Lam_re, const float* __restrict__ Lam_im,
    const float* __restrict__ P_re,   const float* __restrict__ P_im,
    const float* __restrict__ B_re,   const float* __restrict__ B_im,
    const float* __restrict__ log_dt)
{
    if (threadIdx.x != 0) return;
    const int d = blockIdx.x;
    const float scal = 2.0f * expf(-log_dt[d]);
    const float w0 = (float)(-6.283185307179586476925286766559 / (double)SEQ_L);

    float zs, zc;
    sincosf(w0 * (float)HALF_L, &zs, &zc);
    float dzr = 1.1920929e-7f, dzi = 0.0f;   // reference eps clamp
    float idm = 1.0f / (dzr * dzr + dzi * dzi);
    float nr = 1.0f - zc, ni = -zs;
    float gr = scal * (nr * dzr + ni * dzi) * idm;
    float gi = scal * (ni * dzr - nr * dzi) * idm;
    float pfr = 2.0f * dzr * idm, pfi = -2.0f * dzi * idm;

    float PRBr=0,PRBi=0,BRPr=0,BRPi=0,PRPr=0,PRPi=0,BRBr=0,BRBi=0;
    for (int n = 0; n < STATE_N; n++) {
        const int idx = d * STATE_N + n;
        float lr = Lam_re[idx];
        float li = Lam_im[idx];
        float sp = fmaxf(lr, 0.0f) + log1pf(expf(-fabsf(lr)));
        float pr = P_re[idx], pi = P_im[idx];
        float br = B_re[idx], bi = B_im[idx];
        float w1r = pr * br + pi * bi;
        float w1i = pr * bi - pi * br;
        float pp  = pr * pr + pi * pi;
        float bb  = br * br + bi * bi;
        float dr = gr + sp;
        float di = gi - li;
        float m  = fmaf(dr, dr, di * di);
        float inv = 1.0f / m;
        float Rtr = dr * inv;
        float Rti = -di * inv;
        PRBr += w1r * Rtr - w1i * Rti;
        PRBi += w1r * Rti + w1i * Rtr;
        BRPr += w1r * Rtr + w1i * Rti;
        BRPi += w1r * Rti - w1i * Rtr;
        PRPr += pp * Rtr;  PRPi += pp * Rti;
        BRBr += bb * Rtr;  BRBi += bb * Rti;
    }
    float qr = 1.0f + PRPr, qi = PRPi;
    float iq = 1.0f / (qr * qr + qi * qi);
    float numr = BRPr * PRBr - BRPi * PRBi;
    float numi = BRPr * PRBi + BRPi * PRBr;
    float tr = (numr * qr + numi * qi) * iq;
    float ti = (numi * qr - numr * qi) * iq;
    float hr = BRBr - tr, hi = BRBi - ti;
    g_Khat[d * SEQ_L + HALF_L] = make_float2(pfr * hr - pfi * hi,
                                             pfr * hi + pfi * hr);
}

// ---------------------------------------------------------------------------
// Kernel 2: Re(ifft_L(X)) = Hermitian fold + 4096-pt radix-4 inverse Stockham.
// One CTA per d-row, 64 KB smem ping-pong, 1024 threads.
// ---------------------------------------------------------------------------
__global__ void __launch_bounds__(1024) ifft_kernel(float* __restrict__ out)
{
    extern __shared__ float2 sm[];
    float2* x = sm;
    float2* y = sm + HALF_L;

    const int d   = blockIdx.x;
    const int tid = threadIdx.x;
    const int NT  = 1024;

    const float2* src = g_Khat + d * SEQ_L;

    // Hermitian fold + even/odd pack:  x[k] = E[k] + i*O[k]
    const float thL = 6.28318530717958647692f / (float)SEQ_L;
    for (int kk = tid; kk < HALF_L; kk += NT) {
        float2 Xa  = src[kk];
        float2 Xam = src[kk == 0 ? 0 : SEQ_L - kk];
        float2 Xb  = src[kk + HALF_L];
        float2 Xbm = src[HALF_L - kk];
        float Ar = 0.5f * (Xa.x + Xam.x), Ai = 0.5f * (Xa.y - Xam.y);
        float Br = 0.5f * (Xb.x + Xbm.x), Bi = 0.5f * (Xb.y - Xbm.y);
        float Er = 0.5f * (Ar + Br), Ei = 0.5f * (Ai + Bi);
        float Dr = 0.5f * (Ar - Br), Di = 0.5f * (Ai - Bi);
        float swr, swi;
        __sincosf(thL * (float)kk, &swi, &swr);
        float Or = Dr * swr - Di * swi;
        float Oi = Dr * swi + Di * swr;
        x[kk] = make_float2(Er - Oi, Ei + Or);
    }
    __syncthreads();

    int n = HALF_L, s = 1, ls = 0;
    while (n > 1) {
        const int m = n >> 2;
        const float th = 6.28318530717958647692f / (float)n;
        for (int u = tid; u < (HALF_L >> 2); u += NT) {
            int p = u >> ls;
            int q = u & (s - 1);
            int base = q + s * p;
            float2 a  = x[base];
            float2 b  = x[base + s * m];
            float2 c  = x[base + s * 2 * m];
            float2 dd = x[base + s * 3 * m];

            float w1i, w1r;
            __sincosf(th * (float)p, &w1i, &w1r);
            float w2r = w1r * w1r - w1i * w1i;
            float w2i = 2.0f * w1r * w1i;
            float w3r = w2r * w1r - w2i * w1i;
            float w3i = w2r * w1i + w2i * w1r;

            float acr = a.x + c.x, aci = a.y + c.y;
            float amr = a.x - c.x, ami = a.y - c.y;
            float bdr = b.x + dd.x, bdi = b.y + dd.y;
            float bmr = b.x - dd.x, bmi = b.y - dd.y;

            float X0r = acr + bdr, X0i = aci + bdi;
            float X2r = acr - bdr, X2i = aci - bdi;
            float X1r = amr - bmi, X1i = ami + bmr;
            float X3r = amr + bmi, X3i = ami - bmr;

            int ob = q + s * 4 * p;
            y[ob]         = make_float2(X0r, X0i);
            y[ob + s]     = make_float2(X1r * w1r - X1i * w1i,
                                        X1r * w1i + X1i * w1r);
            y[ob + 2 * s] = make_float2(X2r * w2r - X2i * w2i,
                                        X2r * w2i + X2i * w2r);
            y[ob + 3 * s] = make_float2(X3r * w3r - X3i * w3i,
                                        X3r * w3i + X3i * w3r);
        }
        __syncthreads();
        float2* tmp = x; x = y; y = tmp;
        n = m; s <<= 2; ls += 2;
    }

    const float scale = 1.0f / (float)HALF_L;
    float* dstp = out + d * SEQ_L;
    for (int mI = tid; mI < HALF_L; mI += NT) {
        float2 v = x[mI];
        dstp[2 * mI]     = v.x * scale;
        dstp[2 * mI + 1] = v.y * scale;
    }
}

// ---------------------------------------------------------------------------
extern "C" void kernel_launch(void* const* d_in, const int* in_sizes, int n_in,
                              void* d_out, int out_size)
{
    const float* Lam_re = (const float*)d_in[0];
    const float* Lam_im = (const float*)d_in[1];
    const float* P_re   = (const float*)d_in[2];
    const float* P_im   = (const float*)d_in[3];
    const float* B_re   = (const float*)d_in[4];
    const float* B_im   = (const float*)d_in[5];
    const float* log_dt = (const float*)d_in[6];

    float* out = (float*)d_out;

    // Stage 1: Cauchy + Woodbury via tf32 MMA -> K_hat (full spectrum)
    dim3 gridA(SEQ_L / 1024, D_MODEL);   // 8 x 256
    cauchy_mma<<<gridA, 256>>>(Lam_re, Lam_im, P_re, P_im, B_re, B_im, log_dt);

    // Stage 1b: exact fix of the eps-clamped k = L/2 point
    fix4096<<<D_MODEL, 32>>>(Lam_re, Lam_im, P_re, P_im, B_re, B_im, log_dt);

    // Stage 2: Hermitian fold + radix-4 half-length iFFT per row -> K
    cudaFuncSetAttribute(ifft_kernel,
                         cudaFuncAttributeMaxDynamicSharedMemorySize, 65536);
    ifft_kernel<<<D_MODEL, 1024, 65536>>>(out);

    // Tail of the output: D buffer (zeros in the reference)
    long kElems = (long)D_MODEL * SEQ_L;
    if ((long)out_size > kElems) {
        cudaMemsetAsync(out + kElems, 0,
                        ((long)out_size - kElems) * sizeof(float), 0);
    }
}

// round 11
// speedup vs baseline: 1.2311x; 1.2311x over previous
#include <cuda_runtime.h>
#include <math.h>
#include <stdint.h>

#define D_MODEL 256
#define STATE_N 64
#define SEQ_L   8192
#define HALF_L  4096

// Scratch: K_hat[d, L] complex64 (16 MB) as a device global (no runtime alloc).
__device__ float2 g_Khat[D_MODEL * SEQ_L];

// ---------------------------------------------------------------------------
// tf32 mma (operands: raw f32 bits; HW ignores low 13 mantissa bits = trunc)
// ---------------------------------------------------------------------------
__device__ __forceinline__ void mma_tf32(float& d0, float& d1, float& d2, float& d3,
                                         float a0, float a1, float a2, float a3,
                                         float b0, float b1)
{
    asm volatile(
        "mma.sync.aligned.m16n8k8.row.col.f32.tf32.tf32.f32 "
        "{%0,%1,%2,%3}, {%4,%5,%6,%7}, {%8,%9}, {%0,%1,%2,%3};"
        : "+f"(d0), "+f"(d1), "+f"(d2), "+f"(d3)
        : "r"(__float_as_uint(a0)), "r"(__float_as_uint(a1)),
          "r"(__float_as_uint(a2)), "r"(__float_as_uint(a3)),
          "r"(__float_as_uint(b0)), "r"(__float_as_uint(b1)));
}

__device__ __forceinline__ uint32_t tf32_rna(float x) {
    uint32_t u;
    asm("cvt.rna.tf32.f32 %0, %1;" : "=r"(u) : "f"(x));
    return u;
}

// ---------------------------------------------------------------------------
// Woodbury tail from the 8 fast-path sums (g purely imaginary form).
// ---------------------------------------------------------------------------
__device__ __forceinline__ float2 wb_fast(float SA, float SB, float SC, float SD,
                                          float TA, float TB, float TC, float TD,
                                          float pfr, float pfi)
{
    float PRBr = SA + TB, PRBi = SB - TA;
    float BRPr = SA - TB, BRPi = -SB - TA;
    float qr = 1.0f + SC, qi = -TC;
    float BRBr = SD, BRBi = -TD;
    float iq = 1.0f / (qr * qr + qi * qi);
    float numr = BRPr * PRBr - BRPi * PRBi;
    float numi = BRPr * PRBi + BRPi * PRBr;
    float tr = (numr * qr + numi * qi) * iq;
    float ti = (numi * qr - numr * qi) * iq;
    float hr = BRBr - tr, hi = BRBi - ti;
    return make_float2(pfr * hr - pfi * hi, pfr * hi + pfi * hr);
}

// ---------------------------------------------------------------------------
// Kernel 1: Cauchy + Woodbury via tf32 mma.sync (no cvt, pairwise rcp,
// register-preloaded B fragments, fused k=L/2 exact fix).
// ---------------------------------------------------------------------------
__global__ void __launch_bounds__(256) cauchy_mma(
    const float* __restrict__ Lam_re, const float* __restrict__ Lam_im,
    const float* __restrict__ P_re,   const float* __restrict__ P_im,
    const float* __restrict__ B_re,   const float* __restrict__ B_im,
    const float* __restrict__ log_dt)
{
    __shared__ float2 s_lisp[STATE_N];     // (lam_im, sp*sp)
    __shared__ float  s_Sw[4 * STATE_N];   // tf32-rna S-weights [j][n]
    __shared__ float  s_Tw[4 * STATE_N];   // tf32-rna T-weights [j][n]
    __shared__ float  s_gi[1024], s_pfr[1024], s_pfi[1024];
    __shared__ float  s_sums[8][16][8];    // per-warp D staging
    __shared__ float  s_scal_sh;

    const int d    = blockIdx.y;
    const int seg  = blockIdx.x;
    const int tid  = threadIdx.x;
    const int lane = tid & 31;
    const int warp = tid >> 5;

    if (tid < STATE_N) {
        const int idx = d * STATE_N + tid;
        float lr = Lam_re[idx];
        float li = Lam_im[idx];
        float sp = fmaxf(lr, 0.0f) + log1pf(expf(-fabsf(lr)));  // softplus
        float pr = P_re[idx], pi = P_im[idx];
        float br = B_re[idx], bi = B_im[idx];
        float w1r = pr * br + pi * bi;    // conj(P)*B
        float w1i = pr * bi - pi * br;
        float pp  = pr * pr + pi * pi;
        float bb  = br * br + bi * bi;
        s_lisp[tid] = make_float2(li, sp * sp);
        s_Sw[0 * STATE_N + tid] = __uint_as_float(tf32_rna(w1r * sp));
        s_Sw[1 * STATE_N + tid] = __uint_as_float(tf32_rna(w1i * sp));
        s_Sw[2 * STATE_N + tid] = __uint_as_float(tf32_rna(pp * sp));
        s_Sw[3 * STATE_N + tid] = __uint_as_float(tf32_rna(bb * sp));
        s_Tw[0 * STATE_N + tid] = __uint_as_float(tf32_rna(w1r));
        s_Tw[1 * STATE_N + tid] = __uint_as_float(tf32_rna(w1i));
        s_Tw[2 * STATE_N + tid] = __uint_as_float(tf32_rna(pp));
        s_Tw[3 * STATE_N + tid] = __uint_as_float(tf32_rna(bb));
    }
    if (tid == 0) s_scal_sh = 2.0f * expf(-log_dt[d]);
    __syncthreads();

    // per-k prologue: gi, pref (f32 arithmetic matching the reference)
    const float scal = s_scal_sh;
    const float w0 = (float)(-6.283185307179586476925286766559 / (double)SEQ_L);
    for (int kk = tid; kk < 1024; kk += 256) {
        int k = seg * 1024 + kk;
        float zs, zc;
        sincosf(w0 * (float)k, &zs, &zc);
        float dzr = 1.0f + zc, dzi = zs;
        if (k == HALF_L) { dzr = 1.1920929e-7f; dzi = 0.0f; }
        float idm = 1.0f / (dzr * dzr + dzi * dzi);
        float nr = 1.0f - zc, ni = -zs;
        s_gi[kk]  = scal * (ni * dzr - nr * dzi) * idm;
        s_pfr[kk] = 2.0f * dzr * idm;
        s_pfi[kk] = -2.0f * dzi * idm;
    }
    __syncthreads();

    const int j  = lane >> 2;       // output sum column 0..7
    const int qr = lane & 3;

    // Preload B fragments (constant over all tiles): MMA1 uses Sw (cols 0-3),
    // MMA2 uses Tw (cols 4-7); the other half of each is literal zero.
    float pS0[8], pS1[8], pT0[8], pT1[8];
#pragma unroll
    for (int ch = 0; ch < 8; ch++) {
        int n0 = ch * 8 + qr, n1 = n0 + 4;
        if (j < 4) {
            pS0[ch] = s_Sw[j * STATE_N + n0];
            pS1[ch] = s_Sw[j * STATE_N + n1];
            pT0[ch] = 0.f; pT1[ch] = 0.f;
        } else {
            pS0[ch] = 0.f; pS1[ch] = 0.f;
            pT0[ch] = s_Tw[(j - 4) * STATE_N + n0];
            pT1[ch] = s_Tw[(j - 4) * STATE_N + n1];
        }
    }

    for (int t = 0; t < 8; t++) {
        const int base = (warp * 8 + t) * 16;
        const float gi0 = s_gi[base + (lane >> 2)];       // row l/4
        const float gi1 = s_gi[base + 8 + (lane >> 2)];   // row 8 + l/4

        float d0 = 0.f, d1 = 0.f, d2 = 0.f, d3 = 0.f;

#pragma unroll
        for (int ch = 0; ch < 8; ch++) {
            const int n0 = ch * 8 + qr;
            float2 cA = s_lisp[n0];
            float2 cB = s_lisp[n0 + 4];

            // A sites: a0=(r0,n0) a1=(r1,n0) a2=(r0,n1) a3=(r1,n1)
            float di0 = gi0 - cA.x;
            float di1 = gi1 - cA.x;
            float di2 = gi0 - cB.x;
            float di3 = gi1 - cB.x;
            float m0 = fmaf(di0, di0, cA.y);
            float m1 = fmaf(di1, di1, cA.y);
            float m2 = fmaf(di2, di2, cB.y);
            float m3 = fmaf(di3, di3, cB.y);
            // pairwise reciprocal: 2 MUFU instead of 4
            float p01, p23;
            float q01 = m0 * m1, q23 = m2 * m3;
            asm("rcp.approx.f32 %0, %1;" : "=f"(p01) : "f"(q01));
            asm("rcp.approx.f32 %0, %1;" : "=f"(p23) : "f"(q23));
            float i0 = p01 * m1, i1 = p01 * m0;
            float i2 = p23 * m3, i3 = p23 * m2;
            float r0 = di0 * i0, r1 = di1 * i1;
            float r2 = di2 * i2, r3 = di3 * i3;

            mma_tf32(d0, d1, d2, d3, i0, i1, i2, i3, pS0[ch], pS1[ch]);
            mma_tf32(d0, d1, d2, d3, r0, r1, r2, r3, pT0[ch], pT1[ch]);
        }

        // epilogue: stage D to smem, lanes 0..15 run Woodbury for 16 k's
        float (*sw)[8] = s_sums[warp];
        sw[lane >> 2][2 * qr]           = d0;
        sw[lane >> 2][2 * qr + 1]       = d1;
        sw[8 + (lane >> 2)][2 * qr]     = d2;
        sw[8 + (lane >> 2)][2 * qr + 1] = d3;
        __syncwarp();
        if (lane < 16) {
            float SA = sw[lane][0], SB = sw[lane][1];
            float SC = sw[lane][2], SD = sw[lane][3];
            float TA = sw[lane][4], TB = sw[lane][5];
            float TC = sw[lane][6], TD = sw[lane][7];
            int kk = base + lane;
            float2 r = wb_fast(SA, SB, SC, SD, TA, TB, TC, TD,
                               s_pfr[kk], s_pfi[kk]);
            g_Khat[d * SEQ_L + seg * 1024 + kk] = r;
        }
        __syncwarp();
    }

    // ---- exact fix of the eps-clamped point k = L/2 (same thread that wrote
    // it in the tile loop: seg 4, warp 0, tile 0, lane 0 — program-ordered) ----
    if (seg == 4 && tid == 0) {
        float zs, zc;
        sincosf(w0 * (float)HALF_L, &zs, &zc);
        float dzr = 1.1920929e-7f, dzi = 0.0f;
        float idm = 1.0f / (dzr * dzr + dzi * dzi);
        float nr = 1.0f - zc, ni = -zs;
        float gr = scal * (nr * dzr + ni * dzi) * idm;
        float gi = scal * (ni * dzr - nr * dzi) * idm;
        float pfr = 2.0f * dzr * idm, pfi = -2.0f * dzi * idm;

        float PRBr=0,PRBi=0,BRPr=0,BRPi=0,PRPr=0,PRPi=0,BRBr=0,BRBi=0;
        for (int n = 0; n < STATE_N; n++) {
            const int idx = d * STATE_N + n;
            float lr = Lam_re[idx];
            float li = Lam_im[idx];
            float sp = fmaxf(lr, 0.0f) + log1pf(expf(-fabsf(lr)));
            float pr = P_re[idx], pi = P_im[idx];
            float br = B_re[idx], bi = B_im[idx];
            float w1r = pr * br + pi * bi;
            float w1i = pr * bi - pi * br;
            float pp  = pr * pr + pi * pi;
            float bb  = br * br + bi * bi;
            float dr = gr + sp;
            float di = gi - li;
            float m  = fmaf(dr, dr, di * di);
            float inv = 1.0f / m;
            float Rtr = dr * inv;
            float Rti = -di * inv;
            PRBr += w1r * Rtr - w1i * Rti;
            PRBi += w1r * Rti + w1i * Rtr;
            BRPr += w1r * Rtr + w1i * Rti;
            BRPi += w1r * Rti - w1i * Rtr;
            PRPr += pp * Rtr;  PRPi += pp * Rti;
            BRBr += bb * Rtr;  BRBi += bb * Rti;
        }
        float qr2 = 1.0f + PRPr, qi2 = PRPi;
        float iq = 1.0f / (qr2 * qr2 + qi2 * qi2);
        float numr = BRPr * PRBr - BRPi * PRBi;
        float numi = BRPr * PRBi + BRPi * PRBr;
        float tr = (numr * qr2 + numi * qi2) * iq;
        float ti = (numi * qr2 - numr * qi2) * iq;
        float hr = BRBr - tr, hi = BRBi - ti;
        g_Khat[d * SEQ_L + HALF_L] = make_float2(pfr * hr - pfi * hi,
                                                 pfr * hi + pfi * hr);
    }
}

// ---------------------------------------------------------------------------
// Kernel 2: Re(ifft_L(X)) = Hermitian fold + 4096-pt radix-4 inverse Stockham.
// One CTA per d-row, 64 KB smem ping-pong, 1024 threads.
// ---------------------------------------------------------------------------
__global__ void __launch_bounds__(1024) ifft_kernel(float* __restrict__ out)
{
    extern __shared__ float2 sm[];
    float2* x = sm;
    float2* y = sm + HALF_L;

    const int d   = blockIdx.x;
    const int tid = threadIdx.x;
    const int NT  = 1024;

    const float2* src = g_Khat + d * SEQ_L;

    // Hermitian fold + even/odd pack:  x[k] = E[k] + i*O[k]
    const float thL = 6.28318530717958647692f / (float)SEQ_L;
    for (int kk = tid; kk < HALF_L; kk += NT) {
        float2 Xa  = src[kk];
        float2 Xam = src[kk == 0 ? 0 : SEQ_L - kk];
        float2 Xb  = src[kk + HALF_L];
        float2 Xbm = src[HALF_L - kk];
        float Ar = 0.5f * (Xa.x + Xam.x), Ai = 0.5f * (Xa.y - Xam.y);
        float Br = 0.5f * (Xb.x + Xbm.x), Bi = 0.5f * (Xb.y - Xbm.y);
        float Er = 0.5f * (Ar + Br), Ei = 0.5f * (Ai + Bi);
        float Dr = 0.5f * (Ar - Br), Di = 0.5f * (Ai - Bi);
        float swr, swi;
        __sincosf(thL * (float)kk, &swi, &swr);
        float Or = Dr * swr - Di * swi;
        float Oi = Dr * swi + Di * swr;
        x[kk] = make_float2(Er - Oi, Ei + Or);
    }
    __syncthreads();

    int n = HALF_L, s = 1, ls = 0;
    while (n > 1) {
        const int m = n >> 2;
        const float th = 6.28318530717958647692f / (float)n;
        for (int u = tid; u < (HALF_L >> 2); u += NT) {
            int p = u >> ls;
            int q = u & (s - 1);
            int base = q + s * p;
            float2 a  = x[base];
            float2 b  = x[base + s * m];
            float2 c  = x[base + s * 2 * m];
            float2 dd = x[base + s * 3 * m];

            float w1i, w1r;
            __sincosf(th * (float)p, &w1i, &w1r);
            float w2r = w1r * w1r - w1i * w1i;
            float w2i = 2.0f * w1r * w1i;
            float w3r = w2r * w1r - w2i * w1i;
            float w3i = w2r * w1i + w2i * w1r;

            float acr = a.x + c.x, aci = a.y + c.y;
            float amr = a.x - c.x, ami = a.y - c.y;
            float bdr = b.x + dd.x, bdi = b.y + dd.y;
            float bmr = b.x - dd.x, bmi = b.y - dd.y;

            float X0r = acr + bdr, X0i = aci + bdi;
            float X2r = acr - bdr, X2i = aci - bdi;
            float X1r = amr - bmi, X1i = ami + bmr;
            float X3r = amr + bmi, X3i = ami - bmr;

            int ob = q + s * 4 * p;
            y[ob]         = make_float2(X0r, X0i);
            y[ob + s]     = make_float2(X1r * w1r - X1i * w1i,
                                        X1r * w1i + X1i * w1r);
            y[ob + 2 * s] = make_float2(X2r * w2r - X2i * w2i,
                                        X2r * w2i + X2i * w2r);
            y[ob + 3 * s] = make_float2(X3r * w3r - X3i * w3i,
                                        X3r * w3i + X3i * w3r);
        }
        __syncthreads();
        float2* tmp = x; x = y; y = tmp;
        n = m; s <<= 2; ls += 2;
    }

    const float scale = 1.0f / (float)HALF_L;
    float* dstp = out + d * SEQ_L;
    for (int mI = tid; mI < HALF_L; mI += NT) {
        float2 v = x[mI];
        dstp[2 * mI]     = v.x * scale;
        dstp[2 * mI + 1] = v.y * scale;
    }
}

// ---------------------------------------------------------------------------
extern "C" void kernel_launch(void* const* d_in, const int* in_sizes, int n_in,
                              void* d_out, int out_size)
{
    const float* Lam_re = (const float*)d_in[0];
    const float* Lam_im = (const float*)d_in[1];
    const float* P_re   = (const float*)d_in[2];
    const float* P_im   = (const float*)d_in[3];
    const float* B_re   = (const float*)d_in[4];
    const float* B_im   = (const float*)d_in[5];
    const float* log_dt = (const float*)d_in[6];

    float* out = (float*)d_out;

    // Stage 1: Cauchy + Woodbury via tf32 MMA (incl. exact k=L/2 fix)
    dim3 gridA(SEQ_L / 1024, D_MODEL);   // 8 x 256
    cauchy_mma<<<gridA, 256>>>(Lam_re, Lam_im, P_re, P_im, B_re, B_im, log_dt);

    // Stage 2: Hermitian fold + radix-4 half-length iFFT per row -> K
    cudaFuncSetAttribute(ifft_kernel,
                         cudaFuncAttributeMaxDynamicSharedMemorySize, 65536);
    ifft_kernel<<<D_MODEL, 1024, 65536>>>(out);

    // Tail of the output: D buffer (zeros in the reference)
    long kElems = (long)D_MODEL * SEQ_L;
    if ((long)out_size > kElems) {
        cudaMemsetAsync(out + kElems, 0,
                        ((long)out_size - kElems) * sizeof(float), 0);
    }
}